// round 1
// baseline (speedup 1.0000x reference)
#include <cuda_runtime.h>
#include <cstdint>
#include <cstdio>

// ---------------- problem dims (fixed by the dataset) ----------------
#define LL 2048     // sequence length
#define HH 2048     // hidden
#define DD 4096     // inner dim
#define NN 16       // state dim
#define RR 128      // dt rank
#define KC 4        // conv width
#define SP (RR + 2*NN)   // 160 = R + 2N
#define CH 32            // scan chunk length
#define NCH (LL/CH)      // 64 chunks

// ---------------- scratch (device globals; no allocs allowed) ----------------
__device__ float g_proj[LL * 2 * DD];        // 64 MB : [L, 2D] in_proj output (hs_raw | gate)
__device__ float g_hs  [LL * DD];            // 32 MB : silu(conv(hs_raw))
__device__ float g_ssmp[LL * SP];            // 1.3MB : hs @ W_x  -> [dt_in | B | C]
__device__ float g_dt  [LL * DD];            // 32 MB : softplus(dt_in @ W_dt + b_dt)
__device__ float g_y2  [LL * DD];            // 32 MB : gated scan output
__device__ float g_ap  [NCH * NN * DD];      // 16 MB : per-chunk prod(dA)
__device__ float g_sloc[NCH * NN * DD];      // 16 MB : per-chunk local state (s0 = 0)
__device__ float g_sinit[NCH * NN * DD];     // 16 MB : per-chunk initial state

// =====================================================================
// SGEMM: C[M,N] (+)= A[M,K] * B[K,N], fp32, 128x128 tile, 8x8/thread.
// gridDim.z > 1 => split-K with atomicAdd (C must be pre-zeroed).
// Requirements: M % 128 == 0, K % 16 == 0, N % 4 == 0 (N itself arbitrary).
// =====================================================================
#define BM 128
#define BN 128
#define BK 16
#define TM 8
#define TN 8

__global__ __launch_bounds__(256) void sgemm_k(
    const float* __restrict__ A, const float* __restrict__ B, float* __restrict__ C,
    int M, int N, int Kdim, int lda, int ldb, int ldc)
{
    __shared__ float As[BK][BM];
    __shared__ float Bs[BK][BN];

    const int tid  = threadIdx.x;
    const int brow = blockIdx.y * BM;
    const int bcol = blockIdx.x * BN;
    const int ksl  = Kdim / gridDim.z;
    const int kbeg = blockIdx.z * ksl;
    const int kend = kbeg + ksl;
    const int tx = tid & 15;
    const int ty = tid >> 4;

    float acc[TM][TN];
#pragma unroll
    for (int i = 0; i < TM; i++)
#pragma unroll
        for (int j = 0; j < TN; j++) acc[i][j] = 0.f;

    for (int k0 = kbeg; k0 < kend; k0 += BK) {
        // ---- load A tile (BM x BK) transposed into As[k][m]; 512 float4, 2/thread
#pragma unroll
        for (int r = 0; r < 2; r++) {
            int item = tid + r * 256;
            int m  = item >> 2;
            int kq = item & 3;
            const float4 v = *reinterpret_cast<const float4*>(
                &A[(size_t)(brow + m) * lda + k0 + kq * 4]);
            As[kq * 4 + 0][m] = v.x;
            As[kq * 4 + 1][m] = v.y;
            As[kq * 4 + 2][m] = v.z;
            As[kq * 4 + 3][m] = v.w;
        }
        // ---- load B tile (BK x BN); guard N edge (zero fill)
#pragma unroll
        for (int r = 0; r < 2; r++) {
            int item = tid + r * 256;
            int kk = item >> 5;
            int nq = item & 31;
            int gc = bcol + nq * 4;
            float4 v = make_float4(0.f, 0.f, 0.f, 0.f);
            if (gc < N)
                v = *reinterpret_cast<const float4*>(&B[(size_t)(k0 + kk) * ldb + gc]);
            *reinterpret_cast<float4*>(&Bs[kk][nq * 4]) = v;
        }
        __syncthreads();

#pragma unroll
        for (int kk = 0; kk < BK; kk++) {
            float a[TM], b[TN];
            *(float4*)&a[0] = *(const float4*)&As[kk][ty * TM];
            *(float4*)&a[4] = *(const float4*)&As[kk][ty * TM + 4];
            *(float4*)&b[0] = *(const float4*)&Bs[kk][tx * TN];
            *(float4*)&b[4] = *(const float4*)&Bs[kk][tx * TN + 4];
#pragma unroll
            for (int i = 0; i < TM; i++)
#pragma unroll
                for (int j = 0; j < TN; j++)
                    acc[i][j] = fmaf(a[i], b[j], acc[i][j]);
        }
        __syncthreads();
    }

    const bool atom = (gridDim.z > 1);
#pragma unroll
    for (int i = 0; i < TM; i++) {
        int gr = brow + ty * TM + i;
#pragma unroll
        for (int j = 0; j < TN; j++) {
            int gc = bcol + tx * TN + j;
            if (gc < N) {
                if (atom) atomicAdd(&C[(size_t)gr * ldc + gc], acc[i][j]);
                else      C[(size_t)gr * ldc + gc] = acc[i][j];
            }
        }
    }
}

// =====================================================================
// Causal depthwise conv (K=4) + SiLU:  hs = silu(conv(proj[:, :D]) + b)
// =====================================================================
__global__ __launch_bounds__(256) void conv_silu_k(
    const float* __restrict__ conv_w, const float* __restrict__ conv_b)
{
    int idx = blockIdx.x * 256 + threadIdx.x;   // over L*D
    int d = idx & (DD - 1);
    int t = idx >> 12;                          // DD = 4096 = 2^12
    float acc = conv_b[d];
#pragma unroll
    for (int k = 0; k < KC; k++) {
        int tt = t - (KC - 1) + k;
        if (tt >= 0)
            acc = fmaf(g_proj[(size_t)tt * (2 * DD) + d], conv_w[k * DD + d], acc);
    }
    float sg = 1.f / (1.f + expf(-acc));
    g_hs[idx] = acc * sg;
}

// =====================================================================
// dt = softplus(dt_raw + b_dt)   (in place on g_dt)
// =====================================================================
__global__ __launch_bounds__(256) void softplus_k(const float* __restrict__ b_dt)
{
    int idx = blockIdx.x * 256 + threadIdx.x;
    int d = idx & (DD - 1);
    float x = g_dt[idx] + b_dt[d];
    float y = (x > 20.f) ? x : log1pf(expf(x));
    g_dt[idx] = y;
}

// =====================================================================
// Chunked scan, phase A: per (chunk, d) compute prod(dA) and chunk-local
// state (starting from 0) for all n.
// =====================================================================
__global__ __launch_bounds__(256) void scanA_k(const float* __restrict__ A_log)
{
    const int c = blockIdx.x >> 4;                       // 16 blocks per chunk
    const int d = ((blockIdx.x & 15) << 8) + threadIdx.x;

    __shared__ float sB[CH][NN];
    for (int i = threadIdx.x; i < CH * NN; i += 256) {
        int tt = i >> 4, n = i & 15;
        sB[tt][n] = g_ssmp[(size_t)(c * CH + tt) * SP + RR + n];
    }
    __syncthreads();

    float Av[NN];
#pragma unroll
    for (int n = 0; n < NN; n++) Av[n] = -expf(A_log[d * NN + n]);

    float s[NN], ap[NN];
#pragma unroll
    for (int n = 0; n < NN; n++) { s[n] = 0.f; ap[n] = 1.f; }

    for (int tt = 0; tt < CH; tt++) {
        const int t = c * CH + tt;
        const float dtv = g_dt[(size_t)t * DD + d];
        const float hv  = g_hs[(size_t)t * DD + d];
        const float cv  = dtv * hv;
#pragma unroll
        for (int n = 0; n < NN; n++) {
            float da = __expf(dtv * Av[n]);
            ap[n] *= da;
            s[n] = fmaf(da, s[n], cv * sB[tt][n]);
        }
    }
#pragma unroll
    for (int n = 0; n < NN; n++) {
        size_t off = ((size_t)c * NN + n) * DD + d;
        g_ap[off]   = ap[n];
        g_sloc[off] = s[n];
    }
}

// =====================================================================
// Phase B: sequential combine across the 64 chunks, per (d, n).
// =====================================================================
__global__ __launch_bounds__(256) void scanB_k()
{
    int idx = blockIdx.x * 256 + threadIdx.x;   // D*N = 65536 threads
    int d = idx & (DD - 1);
    int n = idx >> 12;
    float s = 0.f;
    for (int c = 0; c < NCH; c++) {
        size_t off = ((size_t)c * NN + n) * DD + d;
        g_sinit[off] = s;
        s = fmaf(g_ap[off], s, g_sloc[off]);
    }
}

// =====================================================================
// Phase C: re-scan with correct initial state, compute y, fuse skip (D),
// and gate: y2 = (y + hs*Dp) * silu(gate)
// =====================================================================
__global__ __launch_bounds__(256) void scanC_k(
    const float* __restrict__ A_log, const float* __restrict__ D_param)
{
    const int c = blockIdx.x >> 4;
    const int d = ((blockIdx.x & 15) << 8) + threadIdx.x;

    __shared__ float sB[CH][NN];
    __shared__ float sC[CH][NN];
    for (int i = threadIdx.x; i < CH * NN; i += 256) {
        int tt = i >> 4, n = i & 15;
        size_t base = (size_t)(c * CH + tt) * SP + RR;
        sB[tt][n] = g_ssmp[base + n];
        sC[tt][n] = g_ssmp[base + NN + n];
    }
    __syncthreads();

    float Av[NN], s[NN];
#pragma unroll
    for (int n = 0; n < NN; n++) {
        Av[n] = -expf(A_log[d * NN + n]);
        s[n]  = g_sinit[((size_t)c * NN + n) * DD + d];
    }
    const float Dp = D_param[d];

    for (int tt = 0; tt < CH; tt++) {
        const int t = c * CH + tt;
        const float dtv = g_dt[(size_t)t * DD + d];
        const float hv  = g_hs[(size_t)t * DD + d];
        const float cv  = dtv * hv;
        float y = 0.f;
#pragma unroll
        for (int n = 0; n < NN; n++) {
            float da = __expf(dtv * Av[n]);
            s[n] = fmaf(da, s[n], cv * sB[tt][n]);
            y = fmaf(s[n], sC[tt][n], y);
        }
        const float g  = g_proj[(size_t)t * (2 * DD) + DD + d];
        const float sg = g / (1.f + expf(-g));
        g_y2[(size_t)t * DD + d] = (y + hv * Dp) * sg;
    }
}

// =====================================================================
// launch
// =====================================================================
extern "C" void kernel_launch(void* const* d_in, const int* in_sizes, int n_in,
                              void* d_out, int out_size)
{
    const float* x       = (const float*)d_in[0];
    const float* W_in    = (const float*)d_in[1];
    const float* conv_w  = (const float*)d_in[2];
    const float* conv_b  = (const float*)d_in[3];
    const float* W_x     = (const float*)d_in[4];
    const float* W_dt    = (const float*)d_in[5];
    const float* b_dt    = (const float*)d_in[6];
    const float* A_log   = (const float*)d_in[7];
    const float* D_param = (const float*)d_in[8];
    const float* W_out   = (const float*)d_in[9];
    float* out = (float*)d_out;

    float *p_proj, *p_hs, *p_ssmp, *p_dt, *p_y2;
    cudaGetSymbolAddress((void**)&p_proj, g_proj);
    cudaGetSymbolAddress((void**)&p_hs,   g_hs);
    cudaGetSymbolAddress((void**)&p_ssmp, g_ssmp);
    cudaGetSymbolAddress((void**)&p_dt,   g_dt);
    cudaGetSymbolAddress((void**)&p_y2,   g_y2);

    // 1) proj = x @ W_in           [2048,2048] x [2048,8192]
    {
        dim3 grid((2 * DD) / BN, LL / BM, 1);
        sgemm_k<<<grid, 256>>>(x, W_in, p_proj, LL, 2 * DD, HH, HH, 2 * DD, 2 * DD);
    }
    // 2) hs = silu(causal depthwise conv)
    conv_silu_k<<<(LL * DD) / 256, 256>>>(conv_w, conv_b);

    // 3) ssm_p = hs @ W_x          [2048,4096] x [4096,160]  (split-K=16)
    cudaMemsetAsync(p_ssmp, 0, sizeof(float) * LL * SP, 0);
    {
        dim3 grid((SP + BN - 1) / BN, LL / BM, 16);
        sgemm_k<<<grid, 256>>>(p_hs, W_x, p_ssmp, LL, SP, DD, DD, SP, SP);
    }
    // 4) dt_raw = dt_in @ W_dt     [2048,128] x [128,4096]   (dt_in strided in ssm_p)
    {
        dim3 grid(DD / BN, LL / BM, 1);
        sgemm_k<<<grid, 256>>>(p_ssmp, W_dt, p_dt, LL, DD, RR, SP, DD, DD);
    }
    // 5) dt = softplus(dt_raw + b_dt)
    softplus_k<<<(LL * DD) / 256, 256>>>(b_dt);

    // 6) chunked linear scan
    scanA_k<<<NCH * (DD / 256), 256>>>(A_log);
    scanB_k<<<(DD * NN) / 256, 256>>>();
    scanC_k<<<NCH * (DD / 256), 256>>>(A_log, D_param);

    // 7) out = y2 @ W_out          [2048,4096] x [4096,2048]
    {
        dim3 grid(HH / BN, LL / BM, 1);
        sgemm_k<<<grid, 256>>>(p_y2, W_out, out, LL, HH, DD, DD, HH, HH);
    }
}

// round 3
// speedup vs baseline: 2.9659x; 2.9659x over previous
#include <cuda_runtime.h>
#include <cuda_bf16.h>
#include <cstdint>

// ---------------- problem dims ----------------
#define LL 2048
#define HH 2048
#define DD 4096
#define NN 16
#define RR 128
#define KC 4
#define SP (RR + 2*NN)     // 160
#define CH 32
#define NCH (LL/CH)        // 64

typedef __nv_bfloat16 bf16;

// ---------------- scratch ----------------
__device__ __align__(256) float g_proj [LL * 2 * DD];
__device__ __align__(256) float g_hs   [LL * DD];
__device__ __align__(256) float g_ssmp [LL * SP];
__device__ __align__(256) float g_dt   [LL * DD];
__device__ __align__(256) float g_ap   [NCH * NN * DD];
__device__ __align__(256) float g_sloc [NCH * NN * DD];
__device__ __align__(256) float g_sinit[NCH * NN * DD];

__device__ __align__(256) bf16 g_xhi[LL*HH],       g_xlo[LL*HH];
__device__ __align__(256) bf16 g_winT_hi[2*DD*HH], g_winT_lo[2*DD*HH];
__device__ __align__(256) bf16 g_hshi[LL*DD],      g_hslo[LL*DD];
__device__ __align__(256) bf16 g_wxT_hi[256*DD],   g_wxT_lo[256*DD];
__device__ __align__(256) bf16 g_dtin_hi[LL*RR],   g_dtin_lo[LL*RR];
__device__ __align__(256) bf16 g_wdtT_hi[DD*RR],   g_wdtT_lo[DD*RR];
__device__ __align__(256) bf16 g_y2hi[LL*DD],      g_y2lo[LL*DD];
__device__ __align__(256) bf16 g_woutT_hi[HH*DD],  g_woutT_lo[HH*DD];

// ---------------- helpers ----------------
__device__ __forceinline__ uint32_t smem_u32(const void* p) {
    uint32_t a;
    asm("{ .reg .u64 t; cvta.to.shared.u64 t, %1; cvt.u32.u64 %0, t; }" : "=r"(a) : "l"(p));
    return a;
}
#define CP16(sa, gp) asm volatile("cp.async.cg.shared.global [%0], [%1], 16;" :: "r"(sa), "l"(gp))
#define CPCOMMIT()   asm volatile("cp.async.commit_group;")
#define CPWAIT1()    asm volatile("cp.async.wait_group 1;")
#define CPWAIT0()    asm volatile("cp.async.wait_group 0;")

__device__ __forceinline__ void ldsm4(uint32_t* r, uint32_t addr) {
    asm volatile("ldmatrix.sync.aligned.m8n8.x4.shared.b16 {%0,%1,%2,%3}, [%4];"
        : "=r"(r[0]), "=r"(r[1]), "=r"(r[2]), "=r"(r[3]) : "r"(addr));
}
__device__ __forceinline__ void mma16816(float* d, const uint32_t* a, const uint32_t* b) {
    asm volatile("mma.sync.aligned.m16n8k16.row.col.f32.bf16.bf16.f32 "
        "{%0,%1,%2,%3}, {%4,%5,%6,%7}, {%8,%9}, {%0,%1,%2,%3};"
        : "+f"(d[0]), "+f"(d[1]), "+f"(d[2]), "+f"(d[3])
        : "r"(a[0]), "r"(a[1]), "r"(a[2]), "r"(a[3]), "r"(b[0]), "r"(b[1]));
}
__device__ __forceinline__ void split2(float v, bf16& h, bf16& l) {
    h = __float2bfloat16(v);
    l = __float2bfloat16(v - __bfloat162float(h));
}

// =====================================================================
// split-bf16 tensor GEMM via mma.sync:  C[M,N] = A[M,K] @ B^T (B stored [N,K])
// tile 128x128, BK=64 bf16, double buffered cp.async, XOR-swizzled smem.
// stage layout: Ahi(16K) Alo(16K) Bhi(16K) Blo(16K) = 64KB
// mode: 0 = store, 1 = softplus(x + bias[col]), 2 = atomicAdd
// =====================================================================
#define TBK 64
#define TILE_B 16384
#define STAGE_B 65536
#define SMEM_TOTAL (2 * STAGE_B)

__device__ __forceinline__ void load_chunk(
    uint32_t st, int tid, int K, int kc,
    const bf16* __restrict__ a0, const bf16* __restrict__ a1,
    const bf16* __restrict__ b0, const bf16* __restrict__ b1)
{
    const bf16* ptr[4] = { a0, a1, b0, b1 };
#pragma unroll
    for (int t = 0; t < 4; t++) {
        const bf16* g = ptr[t] + kc;
#pragma unroll
        for (int q = 0; q < 4; q++) {
            int idx = q * 256 + tid;          // 0..1023 per tile
            int row = idx >> 3, c = idx & 7;
            uint32_t so = (uint32_t)(row * 128 + ((c ^ (row & 7)) << 4));
            CP16(st + t * TILE_B + so, g + (size_t)row * K + c * 8);
        }
    }
}

__global__ void __launch_bounds__(256, 1) tgemm_k(
    const bf16* __restrict__ Ahi, const bf16* __restrict__ Alo,
    const bf16* __restrict__ Bhi, const bf16* __restrict__ Blo,
    float* __restrict__ C, int K, int ldc, int n_valid, int mode,
    const float* __restrict__ bias)
{
    extern __shared__ char smem[];
    const uint32_t sb = smem_u32(smem);
    const int tid = threadIdx.x, wid = tid >> 5, lane = tid & 31;
    const int wm = (wid >> 2) * 64;           // warp row offset (2 x 4 warp grid)
    const int wn = (wid & 3) * 32;            // warp col offset
    const int brow = blockIdx.y * 128;
    const int bcol = blockIdx.x * 128;
    const int ksl  = K / gridDim.z;
    const int kbeg = blockIdx.z * ksl;
    const int nch  = ksl / TBK;

    const bf16* a0 = Ahi + (size_t)brow * K;
    const bf16* a1 = Alo + (size_t)brow * K;
    const bf16* b0 = Bhi + (size_t)bcol * K;
    const bf16* b1 = Blo + (size_t)bcol * K;

    float acc[4][4][4];
#pragma unroll
    for (int i = 0; i < 4; i++)
#pragma unroll
        for (int j = 0; j < 4; j++)
#pragma unroll
            for (int e = 0; e < 4; e++) acc[i][j][e] = 0.f;

    load_chunk(sb, tid, K, kbeg, a0, a1, b0, b1);
    CPCOMMIT();

    for (int c = 0; c < nch; c++) {
        if (c + 1 < nch) {
            load_chunk(sb + ((c + 1) & 1) * STAGE_B, tid, K, kbeg + (c + 1) * TBK,
                       a0, a1, b0, b1);
            CPCOMMIT();
            CPWAIT1();
        } else {
            CPWAIT0();
        }
        __syncthreads();

        const uint32_t st = sb + (c & 1) * STAGE_B;
#pragma unroll
        for (int ks = 0; ks < 4; ks++) {
            uint32_t ah[4][4], al[4][4];
#pragma unroll
            for (int i = 0; i < 4; i++) {
                int row = wm + i * 16 + (lane & 15);
                int ch  = ks * 2 + (lane >> 4);
                uint32_t ad = st + row * 128 + ((ch ^ (row & 7)) << 4);
                ldsm4(ah[i], ad);
                ldsm4(al[i], ad + TILE_B);
            }
            uint32_t bh[4][2], bl[4][2];
#pragma unroll
            for (int jj = 0; jj < 2; jj++) {
                int row = wn + jj * 16 + ((lane >> 4) & 1) * 8 + (lane & 7);
                int ch  = ks * 2 + ((lane >> 3) & 1);
                uint32_t ad = st + 2 * TILE_B + row * 128 + ((ch ^ (row & 7)) << 4);
                uint32_t r[4];
                ldsm4(r, ad);
                bh[jj*2][0] = r[0]; bh[jj*2][1] = r[1];
                bh[jj*2+1][0] = r[2]; bh[jj*2+1][1] = r[3];
                ldsm4(r, ad + TILE_B);
                bl[jj*2][0] = r[0]; bl[jj*2][1] = r[1];
                bl[jj*2+1][0] = r[2]; bl[jj*2+1][1] = r[3];
            }
#pragma unroll
            for (int i = 0; i < 4; i++)
#pragma unroll
                for (int j = 0; j < 4; j++) {
                    mma16816(acc[i][j], ah[i], bh[j]);
                    mma16816(acc[i][j], ah[i], bl[j]);
                    mma16816(acc[i][j], al[i], bh[j]);
                }
        }
        __syncthreads();
    }

    // epilogue
    const int qr = lane >> 2, qc = (lane & 3) * 2;
#pragma unroll
    for (int i = 0; i < 4; i++) {
#pragma unroll
        for (int j = 0; j < 4; j++) {
            int gr = brow + wm + i * 16 + qr;
            int gc = bcol + wn + j * 8 + qc;
            float* d = acc[i][j];
            if (mode == 0) {
                if (gc < n_valid) {
                    *reinterpret_cast<float2*>(&C[(size_t)gr * ldc + gc]) =
                        make_float2(d[0], d[1]);
                    *reinterpret_cast<float2*>(&C[(size_t)(gr + 8) * ldc + gc]) =
                        make_float2(d[2], d[3]);
                }
            } else if (mode == 1) {
                float x0 = d[0] + bias[gc],     x1 = d[1] + bias[gc + 1];
                float x2 = d[2] + bias[gc],     x3 = d[3] + bias[gc + 1];
                float y0 = (x0 > 20.f) ? x0 : log1pf(expf(x0));
                float y1 = (x1 > 20.f) ? x1 : log1pf(expf(x1));
                float y2 = (x2 > 20.f) ? x2 : log1pf(expf(x2));
                float y3 = (x3 > 20.f) ? x3 : log1pf(expf(x3));
                C[(size_t)gr * ldc + gc]           = y0;
                C[(size_t)gr * ldc + gc + 1]       = y1;
                C[(size_t)(gr + 8) * ldc + gc]     = y2;
                C[(size_t)(gr + 8) * ldc + gc + 1] = y3;
            } else {
                if (gc < n_valid) {
                    atomicAdd(&C[(size_t)gr * ldc + gc],           d[0]);
                    atomicAdd(&C[(size_t)gr * ldc + gc + 1],       d[1]);
                    atomicAdd(&C[(size_t)(gr + 8) * ldc + gc],     d[2]);
                    atomicAdd(&C[(size_t)(gr + 8) * ldc + gc + 1], d[3]);
                }
            }
        }
    }
}

// =====================================================================
// conversions
// =====================================================================
__global__ __launch_bounds__(256) void split_k(
    const float* __restrict__ src, bf16* __restrict__ hi, bf16* __restrict__ lo, int n)
{
    int i = blockIdx.x * 256 + threadIdx.x;
    if (i < n) { bf16 h, l; split2(src[i], h, l); hi[i] = h; lo[i] = l; }
}

__global__ __launch_bounds__(256) void dtin_split_k()
{
    int i = blockIdx.x * 256 + threadIdx.x;   // LL*RR
    int t = i >> 7, r = i & 127;
    bf16 h, l;
    split2(g_ssmp[(size_t)t * SP + r], h, l);
    g_dtin_hi[i] = h; g_dtin_lo[i] = l;
}

// transpose + split + pad: src [Rw, Cs] fp32 -> out [Cpad, Rw] bf16
__global__ void convT_k(const float* __restrict__ src,
                        bf16* __restrict__ hi, bf16* __restrict__ lo, int Rw, int Cs)
{
    __shared__ float t32[32][33];
    const int r0 = blockIdx.x * 32, c0 = blockIdx.y * 32;
    const int tx = threadIdx.x, ty = threadIdx.y;
#pragma unroll
    for (int i = 0; i < 4; i++) {
        int r = r0 + ty + i * 8, c = c0 + tx;
        t32[ty + i * 8][tx] = (c < Cs) ? src[(size_t)r * Cs + c] : 0.f;
    }
    __syncthreads();
#pragma unroll
    for (int i = 0; i < 4; i++) {
        int oc = ty + i * 8;
        float v = t32[tx][oc];
        bf16 h, l; split2(v, h, l);
        size_t o = (size_t)(c0 + oc) * Rw + r0 + tx;
        hi[o] = h; lo[o] = l;
    }
}

// =====================================================================
// conv + silu (emits fp32 hs and split-bf16 hs)
// =====================================================================
__global__ __launch_bounds__(256) void conv_silu_k(
    const float* __restrict__ conv_w, const float* __restrict__ conv_b)
{
    int idx = blockIdx.x * 256 + threadIdx.x;
    int d = idx & (DD - 1);
    int t = idx >> 12;
    float acc = conv_b[d];
#pragma unroll
    for (int k = 0; k < KC; k++) {
        int tt = t - (KC - 1) + k;
        if (tt >= 0)
            acc = fmaf(g_proj[(size_t)tt * (2 * DD) + d], conv_w[k * DD + d], acc);
    }
    float sg = 1.f / (1.f + expf(-acc));
    float h = acc * sg;
    g_hs[idx] = h;
    bf16 bh, bl; split2(h, bh, bl);
    g_hshi[idx] = bh; g_hslo[idx] = bl;
}

// =====================================================================
// chunked scan
// =====================================================================
__global__ __launch_bounds__(256) void scanA_k(const float* __restrict__ A_log)
{
    const int c = blockIdx.x >> 4;
    const int d = ((blockIdx.x & 15) << 8) + threadIdx.x;

    __shared__ float sB[CH][NN];
    for (int i = threadIdx.x; i < CH * NN; i += 256) {
        int tt = i >> 4, n = i & 15;
        sB[tt][n] = g_ssmp[(size_t)(c * CH + tt) * SP + RR + n];
    }
    __syncthreads();

    float Av[NN];
#pragma unroll
    for (int n = 0; n < NN; n++) Av[n] = -expf(A_log[d * NN + n]);

    float s[NN], ap[NN];
#pragma unroll
    for (int n = 0; n < NN; n++) { s[n] = 0.f; ap[n] = 1.f; }

    for (int tt = 0; tt < CH; tt++) {
        const int t = c * CH + tt;
        const float dtv = g_dt[(size_t)t * DD + d];
        const float hv  = g_hs[(size_t)t * DD + d];
        const float cv  = dtv * hv;
#pragma unroll
        for (int n = 0; n < NN; n++) {
            float da = __expf(dtv * Av[n]);
            ap[n] *= da;
            s[n] = fmaf(da, s[n], cv * sB[tt][n]);
        }
    }
#pragma unroll
    for (int n = 0; n < NN; n++) {
        size_t off = ((size_t)c * NN + n) * DD + d;
        g_ap[off]   = ap[n];
        g_sloc[off] = s[n];
    }
}

__global__ __launch_bounds__(256) void scanB_k()
{
    int idx = blockIdx.x * 256 + threadIdx.x;
    int d = idx & (DD - 1);
    int n = idx >> 12;
    float s = 0.f;
    for (int c = 0; c < NCH; c++) {
        size_t off = ((size_t)c * NN + n) * DD + d;
        g_sinit[off] = s;
        s = fmaf(g_ap[off], s, g_sloc[off]);
    }
}

__global__ __launch_bounds__(256) void scanC_k(
    const float* __restrict__ A_log, const float* __restrict__ D_param)
{
    const int c = blockIdx.x >> 4;
    const int d = ((blockIdx.x & 15) << 8) + threadIdx.x;

    __shared__ float sB[CH][NN];
    __shared__ float sC[CH][NN];
    for (int i = threadIdx.x; i < CH * NN; i += 256) {
        int tt = i >> 4, n = i & 15;
        size_t base = (size_t)(c * CH + tt) * SP + RR;
        sB[tt][n] = g_ssmp[base + n];
        sC[tt][n] = g_ssmp[base + NN + n];
    }
    __syncthreads();

    float Av[NN], s[NN];
#pragma unroll
    for (int n = 0; n < NN; n++) {
        Av[n] = -expf(A_log[d * NN + n]);
        s[n]  = g_sinit[((size_t)c * NN + n) * DD + d];
    }
    const float Dp = D_param[d];

    for (int tt = 0; tt < CH; tt++) {
        const int t = c * CH + tt;
        const float dtv = g_dt[(size_t)t * DD + d];
        const float hv  = g_hs[(size_t)t * DD + d];
        const float cv  = dtv * hv;
        float y = 0.f;
#pragma unroll
        for (int n = 0; n < NN; n++) {
            float da = __expf(dtv * Av[n]);
            s[n] = fmaf(da, s[n], cv * sB[tt][n]);
            y = fmaf(s[n], sC[tt][n], y);
        }
        const float g  = g_proj[(size_t)t * (2 * DD) + DD + d];
        const float sg = g / (1.f + expf(-g));
        float y2 = (y + hv * Dp) * sg;
        bf16 bh, bl; split2(y2, bh, bl);
        size_t o = (size_t)t * DD + d;
        g_y2hi[o] = bh; g_y2lo[o] = bl;
    }
}

// =====================================================================
// launch
// =====================================================================
extern "C" void kernel_launch(void* const* d_in, const int* in_sizes, int n_in,
                              void* d_out, int out_size)
{
    const float* x       = (const float*)d_in[0];
    const float* W_in    = (const float*)d_in[1];
    const float* conv_w  = (const float*)d_in[2];
    const float* conv_b  = (const float*)d_in[3];
    const float* W_x     = (const float*)d_in[4];
    const float* W_dt    = (const float*)d_in[5];
    const float* b_dt    = (const float*)d_in[6];
    const float* A_log   = (const float*)d_in[7];
    const float* D_param = (const float*)d_in[8];
    const float* W_out   = (const float*)d_in[9];
    float* out = (float*)d_out;

    cudaFuncSetAttribute(tgemm_k, cudaFuncAttributeMaxDynamicSharedMemorySize, SMEM_TOTAL);

    float *p_proj, *p_ssmp, *p_dt;
    cudaGetSymbolAddress((void**)&p_proj, g_proj);
    cudaGetSymbolAddress((void**)&p_ssmp, g_ssmp);
    cudaGetSymbolAddress((void**)&p_dt,   g_dt);

    bf16 *xhi, *xlo, *winThi, *winTlo, *hshi, *hslo, *wxThi, *wxTlo;
    bf16 *dtinhi, *dtinlo, *wdtThi, *wdtTlo, *y2hi, *y2lo, *woutThi, *woutTlo;
    cudaGetSymbolAddress((void**)&xhi, g_xhi);        cudaGetSymbolAddress((void**)&xlo, g_xlo);
    cudaGetSymbolAddress((void**)&winThi, g_winT_hi); cudaGetSymbolAddress((void**)&winTlo, g_winT_lo);
    cudaGetSymbolAddress((void**)&hshi, g_hshi);      cudaGetSymbolAddress((void**)&hslo, g_hslo);
    cudaGetSymbolAddress((void**)&wxThi, g_wxT_hi);   cudaGetSymbolAddress((void**)&wxTlo, g_wxT_lo);
    cudaGetSymbolAddress((void**)&dtinhi, g_dtin_hi); cudaGetSymbolAddress((void**)&dtinlo, g_dtin_lo);
    cudaGetSymbolAddress((void**)&wdtThi, g_wdtT_hi); cudaGetSymbolAddress((void**)&wdtTlo, g_wdtT_lo);
    cudaGetSymbolAddress((void**)&y2hi, g_y2hi);      cudaGetSymbolAddress((void**)&y2lo, g_y2lo);
    cudaGetSymbolAddress((void**)&woutThi, g_woutT_hi); cudaGetSymbolAddress((void**)&woutTlo, g_woutT_lo);

    // ---- GEMM1: proj = x @ W_in   [2048,2048]x[2048,8192]
    split_k<<<(LL * HH) / 256, 256>>>(x, xhi, xlo, LL * HH);
    convT_k<<<dim3(HH / 32, (2 * DD) / 32), dim3(32, 8)>>>(W_in, winThi, winTlo, HH, 2 * DD);
    tgemm_k<<<dim3((2 * DD) / 128, LL / 128, 1), 256, SMEM_TOTAL>>>(
        xhi, xlo, winThi, winTlo, p_proj, HH, 2 * DD, 2 * DD, 0, nullptr);

    // ---- conv + silu
    conv_silu_k<<<(LL * DD) / 256, 256>>>(conv_w, conv_b);

    // ---- GEMM2: ssm_p = hs @ W_x   [2048,4096]x[4096,160] (split-K=8, atomic)
    convT_k<<<dim3(DD / 32, 256 / 32), dim3(32, 8)>>>(W_x, wxThi, wxTlo, DD, SP);
    cudaMemsetAsync(p_ssmp, 0, sizeof(float) * LL * SP, 0);
    tgemm_k<<<dim3(2, LL / 128, 8), 256, SMEM_TOTAL>>>(
        hshi, hslo, wxThi, wxTlo, p_ssmp, DD, SP, SP, 2, nullptr);

    // ---- GEMM3: dt = softplus(dt_in @ W_dt + b_dt)   [2048,128]x[128,4096]
    dtin_split_k<<<(LL * RR) / 256, 256>>>();
    convT_k<<<dim3(RR / 32, DD / 32), dim3(32, 8)>>>(W_dt, wdtThi, wdtTlo, RR, DD);
    tgemm_k<<<dim3(DD / 128, LL / 128, 1), 256, SMEM_TOTAL>>>(
        dtinhi, dtinlo, wdtThi, wdtTlo, p_dt, RR, DD, DD, 1, b_dt);

    // ---- chunked scan
    scanA_k<<<NCH * (DD / 256), 256>>>(A_log);
    scanB_k<<<(DD * NN) / 256, 256>>>();
    scanC_k<<<NCH * (DD / 256), 256>>>(A_log, D_param);

    // ---- GEMM4: out = y2 @ W_out   [2048,4096]x[4096,2048]
    convT_k<<<dim3(DD / 32, HH / 32), dim3(32, 8)>>>(W_out, woutThi, woutTlo, DD, HH);
    tgemm_k<<<dim3(HH / 128, LL / 128, 1), 256, SMEM_TOTAL>>>(
        y2hi, y2lo, woutThi, woutTlo, out, DD, HH, HH, 0, nullptr);
}